// round 1
// baseline (speedup 1.0000x reference)
#include <cuda_runtime.h>
#include <cuda_bf16.h>

// Problem constants
#define SEQ   4096
#define DMODEL 1024
#define NHEAD 16
#define HDIM  64
#define D3    (3 * DMODEL)

// Scratch buffers (allocation-free rule: __device__ globals)
__device__ float g_qkv[SEQ * D3];       // [s, 3*D]  (q | k | v)
__device__ float g_attn[SEQ * DMODEL];  // [s, D] head-major within D

// ---------------------------------------------------------------------------
// SGEMM with bias: C[M,N] = A[M,K] @ B[K,N] + bias[N]
// BM=128, BN=128, BK=16, 256 threads, 8x8 per thread
// ---------------------------------------------------------------------------
__global__ __launch_bounds__(256)
void gemm_bias_kernel(const float* __restrict__ A,
                      const float* __restrict__ B,
                      const float* __restrict__ bias,
                      float* __restrict__ C,
                      int M, int N, int K)
{
    __shared__ float As[16][132];   // [k][m], padded
    __shared__ float Bs[16][128];   // [k][n]

    const int tid = threadIdx.x;
    const int tx = tid & 15;
    const int ty = tid >> 4;

    const int row0 = blockIdx.y * 128;
    const int col0 = blockIdx.x * 128;

    float acc[8][8];
    #pragma unroll
    for (int i = 0; i < 8; i++)
        #pragma unroll
        for (int j = 0; j < 8; j++)
            acc[i][j] = 0.0f;

    const int ktiles = K >> 4;
    for (int kt = 0; kt < ktiles; kt++) {
        // load A tile 128x16 (512 float4), store transposed into As[k][m]
        #pragma unroll
        for (int f = tid; f < 512; f += 256) {
            int r  = f >> 2;        // 0..127
            int c4 = f & 3;         // 0..3
            const float4 a = *(const float4*)(A + (size_t)(row0 + r) * K + (kt << 4) + (c4 << 2));
            As[(c4 << 2) + 0][r] = a.x;
            As[(c4 << 2) + 1][r] = a.y;
            As[(c4 << 2) + 2][r] = a.z;
            As[(c4 << 2) + 3][r] = a.w;
        }
        // load B tile 16x128 (512 float4), direct
        #pragma unroll
        for (int f = tid; f < 512; f += 256) {
            int r  = f >> 5;        // 0..15
            int c4 = f & 31;        // 0..31
            const float4 b = *(const float4*)(B + (size_t)((kt << 4) + r) * N + col0 + (c4 << 2));
            *(float4*)(&Bs[r][c4 << 2]) = b;
        }
        __syncthreads();

        #pragma unroll
        for (int k = 0; k < 16; k++) {
            float4 a0 = *(const float4*)(&As[k][ty * 8]);
            float4 a1 = *(const float4*)(&As[k][ty * 8 + 4]);
            float4 b0 = *(const float4*)(&Bs[k][tx * 8]);
            float4 b1 = *(const float4*)(&Bs[k][tx * 8 + 4]);
            float ar[8] = {a0.x, a0.y, a0.z, a0.w, a1.x, a1.y, a1.z, a1.w};
            float br[8] = {b0.x, b0.y, b0.z, b0.w, b1.x, b1.y, b1.z, b1.w};
            #pragma unroll
            for (int i = 0; i < 8; i++)
                #pragma unroll
                for (int j = 0; j < 8; j++)
                    acc[i][j] += ar[i] * br[j];
        }
        __syncthreads();
    }

    // epilogue with bias
    #pragma unroll
    for (int i = 0; i < 8; i++) {
        const int r = row0 + ty * 8 + i;
        #pragma unroll
        for (int jc = 0; jc < 2; jc++) {
            const int c = col0 + tx * 8 + jc * 4;
            float4 o;
            o.x = acc[i][jc * 4 + 0] + bias[c + 0];
            o.y = acc[i][jc * 4 + 1] + bias[c + 1];
            o.z = acc[i][jc * 4 + 2] + bias[c + 2];
            o.w = acc[i][jc * 4 + 3] + bias[c + 3];
            *(float4*)(C + (size_t)r * N + c) = o;
        }
    }
}

// ---------------------------------------------------------------------------
// Flash attention (fp32, causal). One CTA = (head, 64-row q block).
// BM=BN=64, HD=64, 256 threads (16x16), each thread 4x4 of S and 4x4 of O.
// K stored d-major with XOR swizzle on float4 groups -> conflict-free reads.
// ---------------------------------------------------------------------------
__global__ __launch_bounds__(256)
void flash_attn_kernel(const float* __restrict__ qkv,
                       float* __restrict__ attn_out)
{
    extern __shared__ float smem[];
    float* Qs = smem;                 // [64][64]  row-major (seq, d)
    float* Ks = smem + 64 * 64;       // [d][col]  swizzled
    float* Vs = smem + 2 * 64 * 64;   // [kseq][d]
    float* Ps = smem + 3 * 64 * 64;   // [row][kseq]

    const int tid = threadIdx.x;
    const int tx = tid & 15;
    const int ty = tid >> 4;

    const int qb = blockIdx.x;
    const int h  = blockIdx.y;
    const int q0 = qb * 64;
    const int hoff = h * HDIM;

    // load Q tile
    #pragma unroll
    for (int f = tid; f < 1024; f += 256) {
        int r  = f >> 4;
        int c4 = f & 15;
        const float4 v = *(const float4*)(qkv + (size_t)(q0 + r) * D3 + hoff + (c4 << 2));
        *(float4*)(Qs + (r << 6) + (c4 << 2)) = v;
    }

    float acc[4][4];
    float m[4], l[4];
    #pragma unroll
    for (int i = 0; i < 4; i++) {
        m[i] = -1e30f;
        l[i] = 0.0f;
        #pragma unroll
        for (int j = 0; j < 4; j++) acc[i][j] = 0.0f;
    }
    __syncthreads();

    const int nkb = qb + 1;
    for (int kb = 0; kb < nkb; kb++) {
        const int k0 = kb * 64;

        // load K (transposed + swizzled) and V (direct)
        #pragma unroll
        for (int f = tid; f < 1024; f += 256) {
            int r  = f >> 4;      // seq within block
            int c4 = f & 15;      // d group
            const float4 kv = *(const float4*)(qkv + (size_t)(k0 + r) * D3 + DMODEL + hoff + (c4 << 2));
            const int rhi = r >> 2, rlo = r & 3;
            const float kvv[4] = {kv.x, kv.y, kv.z, kv.w};
            #pragma unroll
            for (int u = 0; u < 4; u++) {
                const int d = (c4 << 2) + u;
                Ks[(d << 6) + ((rhi ^ (d & 15)) << 2) + rlo] = kvv[u];
            }
            const float4 vv = *(const float4*)(qkv + (size_t)(k0 + r) * D3 + 2 * DMODEL + hoff + (c4 << 2));
            *(float4*)(Vs + (r << 6) + (c4 << 2)) = vv;
        }
        __syncthreads();

        // S = Q @ K^T (scaled)
        float s[4][4];
        #pragma unroll
        for (int i = 0; i < 4; i++)
            #pragma unroll
            for (int j = 0; j < 4; j++) s[i][j] = 0.0f;

        #pragma unroll 8
        for (int d = 0; d < 64; d++) {
            const float4 kf = *(const float4*)(Ks + (d << 6) + ((tx ^ (d & 15)) << 2));
            #pragma unroll
            for (int i = 0; i < 4; i++) {
                const float qv = Qs[((ty * 4 + i) << 6) + d];
                s[i][0] += qv * kf.x;
                s[i][1] += qv * kf.y;
                s[i][2] += qv * kf.z;
                s[i][3] += qv * kf.w;
            }
        }

        const float scale = 0.125f;  // 1/sqrt(64)
        if (kb == qb) {
            #pragma unroll
            for (int i = 0; i < 4; i++)
                #pragma unroll
                for (int j = 0; j < 4; j++) {
                    const int rr = ty * 4 + i, cc = tx * 4 + j;
                    s[i][j] = (cc > rr) ? -1e30f : s[i][j] * scale;
                }
        } else {
            #pragma unroll
            for (int i = 0; i < 4; i++)
                #pragma unroll
                for (int j = 0; j < 4; j++) s[i][j] *= scale;
        }

        // online softmax per row
        #pragma unroll
        for (int i = 0; i < 4; i++) {
            float mx = fmaxf(fmaxf(s[i][0], s[i][1]), fmaxf(s[i][2], s[i][3]));
            #pragma unroll
            for (int o = 8; o >= 1; o >>= 1)
                mx = fmaxf(mx, __shfl_xor_sync(0xffffffffu, mx, o));
            const float mnew = fmaxf(m[i], mx);
            const float corr = __expf(m[i] - mnew);
            float rs = 0.0f;
            #pragma unroll
            for (int j = 0; j < 4; j++) {
                const float p = __expf(s[i][j] - mnew);
                s[i][j] = p;
                rs += p;
            }
            #pragma unroll
            for (int o = 8; o >= 1; o >>= 1)
                rs += __shfl_xor_sync(0xffffffffu, rs, o);
            l[i] = l[i] * corr + rs;
            m[i] = mnew;
            #pragma unroll
            for (int j = 0; j < 4; j++) acc[i][j] *= corr;
            // stash P
            *(float4*)(Ps + ((ty * 4 + i) << 6) + (tx << 2)) =
                make_float4(s[i][0], s[i][1], s[i][2], s[i][3]);
        }
        __syncthreads();

        // O += P @ V
        #pragma unroll 8
        for (int kk = 0; kk < 64; kk++) {
            const float4 vf = *(const float4*)(Vs + (kk << 6) + (tx << 2));
            #pragma unroll
            for (int i = 0; i < 4; i++) {
                const float pv = Ps[((ty * 4 + i) << 6) + kk];
                acc[i][0] += pv * vf.x;
                acc[i][1] += pv * vf.y;
                acc[i][2] += pv * vf.z;
                acc[i][3] += pv * vf.w;
            }
        }
        __syncthreads();
    }

    // epilogue: normalize and write [s, h*HD + d]
    #pragma unroll
    for (int i = 0; i < 4; i++) {
        const float inv = 1.0f / l[i];
        float4 o;
        o.x = acc[i][0] * inv;
        o.y = acc[i][1] * inv;
        o.z = acc[i][2] * inv;
        o.w = acc[i][3] * inv;
        *(float4*)(attn_out + (size_t)(q0 + ty * 4 + i) * DMODEL + hoff + (tx << 2)) = o;
    }
}

// ---------------------------------------------------------------------------
extern "C" void kernel_launch(void* const* d_in, const int* in_sizes, int n_in,
                              void* d_out, int out_size)
{
    const float* x      = (const float*)d_in[0];
    const float* w_qkv  = (const float*)d_in[1];
    const float* b_qkv  = (const float*)d_in[2];
    const float* w_proj = (const float*)d_in[3];
    const float* b_proj = (const float*)d_in[4];
    float* out = (float*)d_out;

    float* qkv_buf = nullptr;
    float* attn_buf = nullptr;
    cudaGetSymbolAddress((void**)&qkv_buf, g_qkv);
    cudaGetSymbolAddress((void**)&attn_buf, g_attn);

    // QKV projection: [4096,1024] @ [1024,3072]
    gemm_bias_kernel<<<dim3(D3 / 128, SEQ / 128), 256>>>(
        x, w_qkv, b_qkv, qkv_buf, SEQ, D3, DMODEL);

    // Flash attention
    const int smem_bytes = 4 * 64 * 64 * sizeof(float);  // 64 KB
    cudaFuncSetAttribute(flash_attn_kernel,
                         cudaFuncAttributeMaxDynamicSharedMemorySize, smem_bytes);
    flash_attn_kernel<<<dim3(SEQ / 64, NHEAD), 256, smem_bytes>>>(qkv_buf, attn_buf);

    // Output projection: [4096,1024] @ [1024,1024]
    gemm_bias_kernel<<<dim3(DMODEL / 128, SEQ / 128), 256>>>(
        attn_buf, w_proj, b_proj, out, SEQ, DMODEL, DMODEL);
}

// round 6
// speedup vs baseline: 1.1485x; 1.1485x over previous
#include <cuda_runtime.h>
#include <cuda_bf16.h>
#include <cstdint>

// Problem constants
#define SEQ    4096
#define DMODEL 1024
#define NHEAD  16
#define HDIM   64
#define D3     (3 * DMODEL)
#define KSPLIT 3072          // split-bf16 K' = 3 * DMODEL

// ---------------------------------------------------------------------------
// Scratch (__device__ globals; allocation-free rule)
// ---------------------------------------------------------------------------
__device__ float g_qkv[SEQ * D3];        // fp32 qkv
__device__ float g_attn[SEQ * DMODEL];   // fp32 attention output
__device__ __nv_bfloat16 g_A1[SEQ * KSPLIT];       // x split       [4096, 3072]
__device__ __nv_bfloat16 g_A2[SEQ * KSPLIT];       // attn split    [4096, 3072]
__device__ __nv_bfloat16 g_Bqkv[D3 * KSPLIT];      // w_qkv^T split [3072, 3072]
__device__ __nv_bfloat16 g_Bproj[DMODEL * KSPLIT]; // w_proj^T split[1024, 3072]

__device__ __forceinline__ uint32_t smem_u32(const void* p) {
    uint32_t a;
    asm("{ .reg .u64 t; cvta.to.shared.u64 t, %1; cvt.u32.u64 %0, t; }" : "=r"(a) : "l"(p));
    return a;
}

// ---------------------------------------------------------------------------
// Prep kernels: fp32 -> split bf16
// A layout: [rows, 3072] = [hi | lo | hi]
// ---------------------------------------------------------------------------
__global__ __launch_bounds__(256)
void split_rows_kernel(const float* __restrict__ in, __nv_bfloat16* __restrict__ out)
{
    int idx = blockIdx.x * 256 + threadIdx.x;        // over rows*1024
    int r = idx >> 10;
    int k = idx & 1023;
    float v = in[idx];
    __nv_bfloat16 hi = __float2bfloat16(v);
    __nv_bfloat16 lo = __float2bfloat16(v - __bfloat162float(hi));
    size_t base = (size_t)r * KSPLIT + k;
    out[base] = hi;
    out[base + 1024] = lo;
    out[base + 2048] = hi;
}

// B layout: w [1024, N] -> out [N, 3072] = [hi | hi | lo]  (transpose + split)
__global__ __launch_bounds__(256)
void split_w_kernel(const float* __restrict__ w, __nv_bfloat16* __restrict__ out, int N)
{
    __shared__ float t[32][33];
    const int n0 = blockIdx.x * 32;
    const int k0 = blockIdx.y * 32;
    const int tx = threadIdx.x;   // 0..31
    const int ty = threadIdx.y;   // 0..7
    #pragma unroll
    for (int j = 0; j < 4; j++)
        t[ty + 8 * j][tx] = w[(size_t)(k0 + ty + 8 * j) * N + n0 + tx];
    __syncthreads();
    #pragma unroll
    for (int j = 0; j < 4; j++) {
        int n = n0 + ty + 8 * j;
        float v = t[tx][ty + 8 * j];
        __nv_bfloat16 hi = __float2bfloat16(v);
        __nv_bfloat16 lo = __float2bfloat16(v - __bfloat162float(hi));
        size_t base = (size_t)n * KSPLIT + k0 + tx;
        out[base] = hi;
        out[base + 1024] = hi;
        out[base + 2048] = lo;
    }
}

// ---------------------------------------------------------------------------
// HMMA GEMM: C[M,N] = A[M,3072] @ B[N,3072]^T + bias
// Tiles: BM=128, BN=128, BK=32. 256 threads = 8 warps, warp tile 32x64.
// mma.sync.m16n8k16 bf16, 3-stage cp.async pipeline.
// smem rows padded to 40 bf16 (80B) -> conflict-free ldmatrix.
// ---------------------------------------------------------------------------
#define HBK      32
#define HPAD     40                          // bf16 elems per smem row
#define HROWB    (HPAD * 2)                  // 80 bytes
#define A_ST     (128 * HROWB)               // 10240
#define B_ST     (128 * HROWB)               // 10240
#define STAGE_B  (A_ST + B_ST)               // 20480
#define HSTAGES  3
#define HSMEM    (HSTAGES * STAGE_B)         // 61440

#define LDMX4(r0, r1, r2, r3, addr) \
    asm volatile("ldmatrix.sync.aligned.m8n8.x4.shared.b16 {%0,%1,%2,%3}, [%4];" \
        : "=r"(r0), "=r"(r1), "=r"(r2), "=r"(r3) : "r"(addr))

#define MMA16816(d, a, b) \
    asm volatile("mma.sync.aligned.m16n8k16.row.col.f32.bf16.bf16.f32 " \
        "{%0,%1,%2,%3}, {%4,%5,%6,%7}, {%8,%9}, {%0,%1,%2,%3};" \
        : "+f"((d)[0]), "+f"((d)[1]), "+f"((d)[2]), "+f"((d)[3]) \
        : "r"((a)[0]), "r"((a)[1]), "r"((a)[2]), "r"((a)[3]), \
          "r"((b)[0]), "r"((b)[1]))

#define CP_ASYNC16(dst, src) \
    asm volatile("cp.async.cg.shared.global [%0], [%1], 16;" :: "r"(dst), "l"(src) : "memory")
#define CP_COMMIT() asm volatile("cp.async.commit_group;" ::: "memory")
#define CP_WAIT1()  asm volatile("cp.async.wait_group 1;" ::: "memory")

__global__ __launch_bounds__(256, 1)
void hmma_gemm_kernel(const __nv_bfloat16* __restrict__ A,
                      const __nv_bfloat16* __restrict__ B,
                      const float* __restrict__ bias,
                      float* __restrict__ C, int N)
{
    extern __shared__ char smem[];
    const uint32_t sb = smem_u32(smem);
    const int tid  = threadIdx.x;
    const int wid  = tid >> 5;
    const int lane = tid & 31;
    const int m0 = blockIdx.y * 128;
    const int n0 = blockIdx.x * 128;
    const int warp_m = wid & 3;         // 0..3 -> 32-row slice
    const int warp_n = wid >> 2;        // 0..1 -> 64-col slice

    float acc[2][8][4];
    #pragma unroll
    for (int mt = 0; mt < 2; mt++)
        #pragma unroll
        for (int nt = 0; nt < 8; nt++)
            #pragma unroll
            for (int i = 0; i < 4; i++)
                acc[mt][nt][i] = 0.0f;

    // per-thread load slots: 2 A chunks + 2 B chunks of 16B per stage
    const int e0 = tid, e1 = tid + 256;        // 0..511
    const int ar0 = e0 >> 2, ac0 = e0 & 3;
    const int ar1 = e1 >> 2, ac1 = e1 & 3;

    const __nv_bfloat16* Ag0 = A + (size_t)(m0 + ar0) * KSPLIT + (ac0 << 3);
    const __nv_bfloat16* Ag1 = A + (size_t)(m0 + ar1) * KSPLIT + (ac1 << 3);
    const __nv_bfloat16* Bg0 = B + (size_t)(n0 + ar0) * KSPLIT + (ac0 << 3);
    const __nv_bfloat16* Bg1 = B + (size_t)(n0 + ar1) * KSPLIT + (ac1 << 3);

    const uint32_t sA0 = sb + ar0 * HROWB + ac0 * 16;
    const uint32_t sA1 = sb + ar1 * HROWB + ac1 * 16;
    const uint32_t sB0 = sb + A_ST + ar0 * HROWB + ac0 * 16;
    const uint32_t sB1 = sb + A_ST + ar1 * HROWB + ac1 * 16;

    auto load_stage = [&](int s, int kt) {
        const uint32_t off = s * STAGE_B;
        const int ke = kt * HBK;
        CP_ASYNC16(sA0 + off, Ag0 + ke);
        CP_ASYNC16(sA1 + off, Ag1 + ke);
        CP_ASYNC16(sB0 + off, Bg0 + ke);
        CP_ASYNC16(sB1 + off, Bg1 + ke);
        CP_COMMIT();
    };

    const int KT = KSPLIT / HBK;   // 96
    load_stage(0, 0);
    load_stage(1, 1);

    // ldmatrix base offsets (within a stage)
    const uint32_t a_row = warp_m * 32 + (lane & 15);
    const uint32_t a_kad = (lane >> 4) << 3;
    const int q = lane >> 3;                   // matrix id 0..3
    const uint32_t b_row = warp_n * 64 + ((q >> 1) << 3) + (lane & 7);
    const uint32_t b_kad = (q & 1) << 3;

    for (int kt = 0; kt < KT; kt++) {
        const int s = kt % HSTAGES;
        CP_WAIT1();
        __syncthreads();
        if (kt + 2 < KT) load_stage((kt + 2) % HSTAGES, kt + 2);

        const uint32_t As = sb + s * STAGE_B;
        const uint32_t Bs = As + A_ST;

        #pragma unroll
        for (int ks = 0; ks < 2; ks++) {
            const int k0 = ks * 16;
            uint32_t a[2][4];
            #pragma unroll
            for (int mt = 0; mt < 2; mt++) {
                uint32_t addr = As + (a_row + mt * 16) * HROWB + (k0 + a_kad) * 2;
                LDMX4(a[mt][0], a[mt][1], a[mt][2], a[mt][3], addr);
            }
            uint32_t b[8][2];
            #pragma unroll
            for (int nt2 = 0; nt2 < 4; nt2++) {
                uint32_t addr = Bs + (b_row + nt2 * 16) * HROWB + (k0 + b_kad) * 2;
                uint32_t r0, r1, r2, r3;
                LDMX4(r0, r1, r2, r3, addr);
                b[nt2 * 2 + 0][0] = r0; b[nt2 * 2 + 0][1] = r1;
                b[nt2 * 2 + 1][0] = r2; b[nt2 * 2 + 1][1] = r3;
            }
            #pragma unroll
            for (int mt = 0; mt < 2; mt++)
                #pragma unroll
                for (int nt = 0; nt < 8; nt++)
                    MMA16816(acc[mt][nt], a[mt], b[nt]);
        }
        __syncthreads();
    }

    // epilogue: thread holds (rows lane/4, lane/4+8) x (col pair 2*(lane%4)) per tile
    const int rbase = m0 + warp_m * 32 + (lane >> 2);
    const int cbase = n0 + warp_n * 64 + ((lane & 3) << 1);
    #pragma unroll
    for (int mt = 0; mt < 2; mt++) {
        #pragma unroll
        for (int nt = 0; nt < 8; nt++) {
            const int c = cbase + nt * 8;
            const float b0 = bias[c], b1 = bias[c + 1];
            const int r0 = rbase + mt * 16;
            float2 v0 = make_float2(acc[mt][nt][0] + b0, acc[mt][nt][1] + b1);
            float2 v1 = make_float2(acc[mt][nt][2] + b0, acc[mt][nt][3] + b1);
            *(float2*)(C + (size_t)r0 * N + c) = v0;
            *(float2*)(C + (size_t)(r0 + 8) * N + c) = v1;
        }
    }
}

// ---------------------------------------------------------------------------
// Flash attention (fp32, causal) — unchanged (known correct)
// ---------------------------------------------------------------------------
__global__ __launch_bounds__(256)
void flash_attn_kernel(const float* __restrict__ qkv,
                       float* __restrict__ attn_out)
{
    extern __shared__ float fsmem[];
    float* Qs = fsmem;
    float* Ks = fsmem + 64 * 64;
    float* Vs = fsmem + 2 * 64 * 64;
    float* Ps = fsmem + 3 * 64 * 64;

    const int tid = threadIdx.x;
    const int tx = tid & 15;
    const int ty = tid >> 4;

    const int qb = blockIdx.x;
    const int h  = blockIdx.y;
    const int q0 = qb * 64;
    const int hoff = h * HDIM;

    #pragma unroll
    for (int f = tid; f < 1024; f += 256) {
        int r  = f >> 4;
        int c4 = f & 15;
        const float4 v = *(const float4*)(qkv + (size_t)(q0 + r) * D3 + hoff + (c4 << 2));
        *(float4*)(Qs + (r << 6) + (c4 << 2)) = v;
    }

    float acc[4][4];
    float m[4], l[4];
    #pragma unroll
    for (int i = 0; i < 4; i++) {
        m[i] = -1e30f; l[i] = 0.0f;
        #pragma unroll
        for (int j = 0; j < 4; j++) acc[i][j] = 0.0f;
    }
    __syncthreads();

    const int nkb = qb + 1;
    for (int kb = 0; kb < nkb; kb++) {
        const int k0 = kb * 64;
        #pragma unroll
        for (int f = tid; f < 1024; f += 256) {
            int r  = f >> 4;
            int c4 = f & 15;
            const float4 kv = *(const float4*)(qkv + (size_t)(k0 + r) * D3 + DMODEL + hoff + (c4 << 2));
            const int rhi = r >> 2, rlo = r & 3;
            const float kvv[4] = {kv.x, kv.y, kv.z, kv.w};
            #pragma unroll
            for (int u = 0; u < 4; u++) {
                const int d = (c4 << 2) + u;
                Ks[(d << 6) + ((rhi ^ (d & 15)) << 2) + rlo] = kvv[u];
            }
            const float4 vv = *(const float4*)(qkv + (size_t)(k0 + r) * D3 + 2 * DMODEL + hoff + (c4 << 2));
            *(float4*)(Vs + (r << 6) + (c4 << 2)) = vv;
        }
        __syncthreads();

        float s[4][4];
        #pragma unroll
        for (int i = 0; i < 4; i++)
            #pragma unroll
            for (int j = 0; j < 4; j++) s[i][j] = 0.0f;

        #pragma unroll 8
        for (int d = 0; d < 64; d++) {
            const float4 kf = *(const float4*)(Ks + (d << 6) + ((tx ^ (d & 15)) << 2));
            #pragma unroll
            for (int i = 0; i < 4; i++) {
                const float qv = Qs[((ty * 4 + i) << 6) + d];
                s[i][0] += qv * kf.x;
                s[i][1] += qv * kf.y;
                s[i][2] += qv * kf.z;
                s[i][3] += qv * kf.w;
            }
        }

        const float scale = 0.125f;
        if (kb == qb) {
            #pragma unroll
            for (int i = 0; i < 4; i++)
                #pragma unroll
                for (int j = 0; j < 4; j++) {
                    const int rr = ty * 4 + i, cc = tx * 4 + j;
                    s[i][j] = (cc > rr) ? -1e30f : s[i][j] * scale;
                }
        } else {
            #pragma unroll
            for (int i = 0; i < 4; i++)
                #pragma unroll
                for (int j = 0; j < 4; j++) s[i][j] *= scale;
        }

        #pragma unroll
        for (int i = 0; i < 4; i++) {
            float mx = fmaxf(fmaxf(s[i][0], s[i][1]), fmaxf(s[i][2], s[i][3]));
            #pragma unroll
            for (int o = 8; o >= 1; o >>= 1)
                mx = fmaxf(mx, __shfl_xor_sync(0xffffffffu, mx, o));
            const float mnew = fmaxf(m[i], mx);
            const float corr = __expf(m[i] - mnew);
            float rs = 0.0f;
            #pragma unroll
            for (int j = 0; j < 4; j++) {
                const float p = __expf(s[i][j] - mnew);
                s[i][j] = p;
                rs += p;
            }
            #pragma unroll
            for (int o = 8; o >= 1; o >>= 1)
                rs += __shfl_xor_sync(0xffffffffu, rs, o);
            l[i] = l[i] * corr + rs;
            m[i] = mnew;
            #pragma unroll
            for (int j = 0; j < 4; j++) acc[i][j] *= corr;
            *(float4*)(Ps + ((ty * 4 + i) << 6) + (tx << 2)) =
                make_float4(s[i][0], s[i][1], s[i][2], s[i][3]);
        }
        __syncthreads();

        #pragma unroll 8
        for (int kk = 0; kk < 64; kk++) {
            const float4 vf = *(const float4*)(Vs + (kk << 6) + (tx << 2));
            #pragma unroll
            for (int i = 0; i < 4; i++) {
                const float pv = Ps[((ty * 4 + i) << 6) + kk];
                acc[i][0] += pv * vf.x;
                acc[i][1] += pv * vf.y;
                acc[i][2] += pv * vf.z;
                acc[i][3] += pv * vf.w;
            }
        }
        __syncthreads();
    }

    #pragma unroll
    for (int i = 0; i < 4; i++) {
        const float inv = 1.0f / l[i];
        float4 o;
        o.x = acc[i][0] * inv;
        o.y = acc[i][1] * inv;
        o.z = acc[i][2] * inv;
        o.w = acc[i][3] * inv;
        *(float4*)(attn_out + (size_t)(q0 + ty * 4 + i) * DMODEL + hoff + (tx << 2)) = o;
    }
}

// ---------------------------------------------------------------------------
// Host side
// ---------------------------------------------------------------------------
extern "C" void kernel_launch(void* const* d_in, const int* in_sizes, int n_in,
                              void* d_out, int out_size)
{
    const float* x      = (const float*)d_in[0];
    const float* w_qkv  = (const float*)d_in[1];
    const float* b_qkv  = (const float*)d_in[2];
    const float* w_proj = (const float*)d_in[3];
    const float* b_proj = (const float*)d_in[4];
    float* out = (float*)d_out;

    float *qkv_buf, *attn_buf;
    __nv_bfloat16 *A1, *A2, *Bqkv, *Bproj;
    cudaGetSymbolAddress((void**)&qkv_buf,  g_qkv);
    cudaGetSymbolAddress((void**)&attn_buf, g_attn);
    cudaGetSymbolAddress((void**)&A1,    g_A1);
    cudaGetSymbolAddress((void**)&A2,    g_A2);
    cudaGetSymbolAddress((void**)&Bqkv,  g_Bqkv);
    cudaGetSymbolAddress((void**)&Bproj, g_Bproj);

    cudaFuncSetAttribute(hmma_gemm_kernel,
                         cudaFuncAttributeMaxDynamicSharedMemorySize, HSMEM);
    cudaFuncSetAttribute(flash_attn_kernel,
                         cudaFuncAttributeMaxDynamicSharedMemorySize, 4 * 64 * 64 * (int)sizeof(float));

    // 1) split inputs to bf16 hi/lo
    split_rows_kernel<<<SEQ * DMODEL / 256, 256>>>(x, A1);
    split_w_kernel<<<dim3(D3 / 32, DMODEL / 32), dim3(32, 8)>>>(w_qkv, Bqkv, D3);
    split_w_kernel<<<dim3(DMODEL / 32, DMODEL / 32), dim3(32, 8)>>>(w_proj, Bproj, DMODEL);

    // 2) QKV GEMM: [4096,3072] = A1 @ Bqkv^T  (HMMA)
    hmma_gemm_kernel<<<dim3(D3 / 128, SEQ / 128), 256, HSMEM>>>(A1, Bqkv, b_qkv, qkv_buf, D3);

    // 3) attention (fp32, unchanged)
    flash_attn_kernel<<<dim3(SEQ / 64, NHEAD), 256, 4 * 64 * 64 * sizeof(float)>>>(qkv_buf, attn_buf);

    // 4) split attention output, out-proj GEMM (HMMA)
    split_rows_kernel<<<SEQ * DMODEL / 256, 256>>>(attn_buf, A2);
    hmma_gemm_kernel<<<dim3(DMODEL / 128, SEQ / 128), 256, HSMEM>>>(A2, Bproj, b_proj, out, DMODEL);
}